// round 7
// baseline (speedup 1.0000x reference)
#include <cuda_runtime.h>
#include <cuda_fp16.h>
#include <cstdint>

// LogicalConsistencyLoss: out = sum_{s,a,b,c} relu(M_ab - M_ac*M_bc) / (R*B)
// where M = fp16(sigmoid(logits)) * mask_a * mask_b per (batch,relation) slice.
// R7: CS 16->32 (4096 CTAs, 16 c's each) -> wave tail 13% -> 2%.

#define B_ 2
#define N_ 512
#define R_ 4
#define S_ (B_ * R_)                   // 8 slices
#define NT (N_ / 128)                  // 4 tiles per dim
#define CS 32                          // c-split: 16 c's per CTA
#define NCTA (NT * NT * CS * S_)       // 4096 cubic CTAs / partials

__device__ __half    g_relh[S_ * N_ * N_];   // 4 MB scratch (L2-resident)
__device__ float     g_part[NCTA];
__device__ unsigned  g_ctr;                  // zero-init; reset by last CTA

// ---------------- Pass 1: sigmoid + mask -> fp16, de-interleave R ----------------
__global__ void sigmoid_mask_kernel(const float* __restrict__ logits,
                                    const int*   __restrict__ masks) {
    int idx = blockIdx.x * blockDim.x + threadIdx.x;  // over B*N*N
    if (idx >= B_ * N_ * N_) return;
    int b   = idx / (N_ * N_);
    int rem = idx - b * (N_ * N_);
    int i   = rem / N_;
    int j   = rem - i * N_;
    float mm = (masks[b * N_ + i] > 0 && masks[b * N_ + j] > 0) ? 1.0f : 0.0f;
    float4 v = ((const float4*)logits)[idx];  // 4 relations of one (b,i,j)
    float p0 = __fdividef(mm, 1.0f + __expf(-v.x));
    float p1 = __fdividef(mm, 1.0f + __expf(-v.y));
    float p2 = __fdividef(mm, 1.0f + __expf(-v.z));
    float p3 = __fdividef(mm, 1.0f + __expf(-v.w));
    g_relh[(b * R_ + 0) * N_ * N_ + rem] = __float2half(p0);
    g_relh[(b * R_ + 1) * N_ * N_ + rem] = __float2half(p1);
    g_relh[(b * R_ + 2) * N_ * N_ + rem] = __float2half(p2);
    g_relh[(b * R_ + 3) * N_ * N_ + rem] = __float2half(p3);
}

// ---------------- Pass 2: cubic relu contraction + fused final reduce ----------
// Grid: x = (a,b) tile (16), y = c-split (32), z = slice (8). 256 threads.
// Thread: 8x8 fp16 M_ab tile as 8x4 half2 regs; 8 half2 accs -> 2 f32.
__global__ void __launch_bounds__(256, 3)
trans_relu_kernel(float* __restrict__ out) {
    const int tile = blockIdx.x;      // 0..15
    const int cblk = blockIdx.y;      // 0..31
    const int sl   = blockIdx.z;      // 0..7
    const __half* __restrict__ M = g_relh + sl * N_ * N_;

    const int a0 = (tile / NT) * 128;
    const int b0 = (tile % NT) * 128;
    const int c0 = cblk * (N_ / CS);  // 16 c's per CTA

    const int tid = threadIdx.x;
    const int tx  = tid & 15;         // b sub-tile
    const int ty  = tid >> 4;         // a sub-tile

    // All 16 c's staged once.
    // sA holds NEGATED + DUPLICATED values: sA[c][2a]=sA[c][2a+1] = -M[a0+a][c]
    // so uint4 LDS yields 4 ready {-a,-a} half2 broadcast pairs.
    __shared__ __align__(16) __half sA[16][256];   // 8 KB
    __shared__ __align__(16) __half sB[16][128];   // 4 KB

    // 8x8 M_ab tile packed as half2 (j,j+1) pairs: 32 regs.
    __half2 mab2[8][4];
#pragma unroll
    for (int i = 0; i < 8; ++i) {
        uint4 q = *(const uint4*)(M + (a0 + ty * 8 + i) * N_ + b0 + tx * 8);
        mab2[i][0] = *(__half2*)&q.x; mab2[i][1] = *(__half2*)&q.y;
        mab2[i][2] = *(__half2*)&q.z; mab2[i][3] = *(__half2*)&q.w;
    }

    // Stage: each thread loads 16 c-values of one A-row or one B-row.
    {
        const int  sr  = tid & 127;
        const bool isB = tid >= 128;
        const __half* rowp = M + ((isB ? b0 : a0) + sr) * N_ + c0;
        uint4 v0 = ((const uint4*)rowp)[0];
        uint4 v1 = ((const uint4*)rowp)[1];
        __half h[16];
        *(uint4*)&h[0] = v0; *(uint4*)&h[8] = v1;
        if (!isB) {
#pragma unroll
            for (int k = 0; k < 16; ++k) {
                __half2 p = __half2half2(__hneg(h[k]));
                *(uint32_t*)&sA[k][2 * sr] = *(uint32_t*)&p;
            }
        } else {
#pragma unroll
            for (int k = 0; k < 16; ++k) sB[k][sr] = h[k];
        }
    }
    __syncthreads();

    float facc[2] = {0.0f, 0.0f};

    // Mainloop: 2 blocks of 8 c's; fp32 promotion between blocks.
#pragma unroll
    for (int cb = 0; cb < 16; cb += 8) {
        __half2 hacc[8];                   // per-i accs: <=32 terms each
#pragma unroll
        for (int i = 0; i < 8; ++i) hacc[i] = __float2half2_rn(0.0f);

#pragma unroll
        for (int cc = 0; cc < 8; ++cc) {
            const int c = cb + cc;
            uint4 A0 = *(const uint4*)&sA[c][ty * 16];
            uint4 A1 = *(const uint4*)&sA[c][ty * 16 + 8];
            uint4 Bv = *(const uint4*)&sB[c][tx * 8];
            __half2 a2[8], b2[4];
            a2[0] = *(__half2*)&A0.x; a2[1] = *(__half2*)&A0.y;
            a2[2] = *(__half2*)&A0.z; a2[3] = *(__half2*)&A0.w;
            a2[4] = *(__half2*)&A1.x; a2[5] = *(__half2*)&A1.y;
            a2[6] = *(__half2*)&A1.z; a2[7] = *(__half2*)&A1.w;
            b2[0] = *(__half2*)&Bv.x; b2[1] = *(__half2*)&Bv.y;
            b2[2] = *(__half2*)&Bv.z; b2[3] = *(__half2*)&Bv.w;
#pragma unroll
            for (int i = 0; i < 8; ++i) {
#pragma unroll
                for (int jp = 0; jp < 4; ++jp) {
                    // fma.rn.relu.f16x2: relu fused into HFMA2 -> 2 fma-pipe
                    // instrs per half2, zero alu-pipe work.
                    hacc[i] = __hadd2(hacc[i],
                                      __hfma2_relu(a2[i], b2[jp], mab2[i][jp]));
                }
            }
        }

        // promote block accumulators to fp32 (tree into 2 accs)
        __half2 h01 = __hadd2(hacc[0], hacc[1]);
        __half2 h23 = __hadd2(hacc[2], hacc[3]);
        __half2 h45 = __hadd2(hacc[4], hacc[5]);
        __half2 h67 = __hadd2(hacc[6], hacc[7]);
        __half2 hA  = __hadd2(h01, h23);   // <=128 terms, max val <128: safe
        __half2 hB  = __hadd2(h45, h67);
        facc[0] += __low2float(hA) + __high2float(hA);
        facc[1] += __low2float(hB) + __high2float(hB);
    }

    // Deterministic block reduction.
    float tsum = facc[0] + facc[1];
#pragma unroll
    for (int off = 16; off > 0; off >>= 1)
        tsum += __shfl_down_sync(0xFFFFFFFFu, tsum, off);

    __shared__ float wred[8];
    if ((tid & 31) == 0) wred[tid >> 5] = tsum;
    __syncthreads();

    // Publish partial, then elect the last-finishing CTA to do the final sum.
    __shared__ bool amLast;
    if (tid == 0) {
        float s = 0.0f;
#pragma unroll
        for (int w = 0; w < 8; ++w) s += wred[w];
        const int part = ((sl * CS + cblk) * (NT * NT)) + tile;
        g_part[part] = s;
        __threadfence();
        unsigned ticket = atomicAdd(&g_ctr, 1u);
        amLast = (ticket == NCTA - 1);
    }
    __syncthreads();

    if (amLast) {
        // Fixed-order deterministic final reduce over all 4096 partials.
        double s = 0.0;
#pragma unroll
        for (int k = 0; k < NCTA / 256; ++k)
            s += (double)g_part[tid + k * 256];
#pragma unroll
        for (int off = 16; off > 0; off >>= 1)
            s += __shfl_down_sync(0xFFFFFFFFu, s, off);
        __shared__ double dw[8];
        if ((tid & 31) == 0) dw[tid >> 5] = s;
        __syncthreads();
        if (tid == 0) {
            double tot = 0.0;
#pragma unroll
            for (int w = 0; w < 8; ++w) tot += dw[w];
            out[0] = (float)(tot / (double)(R_ * B_));
            g_ctr = 0;   // reset for next graph replay
        }
    }
}

extern "C" void kernel_launch(void* const* d_in, const int* in_sizes, int n_in,
                              void* d_out, int out_size) {
    const float* logits = (const float*)d_in[0];
    const int*   masks  = (const int*)d_in[1];
    float*       out    = (float*)d_out;

    sigmoid_mask_kernel<<<(B_ * N_ * N_ + 255) / 256, 256>>>(logits, masks);

    dim3 g2(NT * NT, CS, S_);
    trans_relu_kernel<<<g2, 256>>>(out);
}

// round 8
// speedup vs baseline: 1.0238x; 1.0238x over previous
#include <cuda_runtime.h>
#include <cuda_fp16.h>
#include <cstdint>

// LogicalConsistencyLoss: out = sum_{s,a,b,c} relu(M_ab - M_ac*M_bc) / (R*B)
// where M = fp16(sigmoid(logits)) * mask_a * mask_b per (batch,relation) slice.
// R8: cheap prologue. sA = natural row-major NEGATED copy (4 STS.128);
//     broadcast {-a,-a} pairs built in mainloop via half-lane selectors.

#define B_ 2
#define N_ 512
#define R_ 4
#define S_ (B_ * R_)                   // 8 slices
#define NT (N_ / 128)                  // 4 tiles per dim
#define CS 16                          // c-split: 32 c's per CTA
#define NCTA (NT * NT * CS * S_)       // 2048 cubic CTAs / partials

__device__ __half    g_relh[S_ * N_ * N_];   // 4 MB scratch (L2-resident)
__device__ float     g_part[NCTA];
__device__ unsigned  g_ctr;                  // zero-init; reset by last CTA

// ---------------- Pass 1: sigmoid + mask -> fp16, de-interleave R ----------------
__global__ void sigmoid_mask_kernel(const float* __restrict__ logits,
                                    const int*   __restrict__ masks) {
    int idx = blockIdx.x * blockDim.x + threadIdx.x;  // over B*N*N
    if (idx >= B_ * N_ * N_) return;
    int b   = idx / (N_ * N_);
    int rem = idx - b * (N_ * N_);
    int i   = rem / N_;
    int j   = rem - i * N_;
    float mm = (masks[b * N_ + i] > 0 && masks[b * N_ + j] > 0) ? 1.0f : 0.0f;
    float4 v = ((const float4*)logits)[idx];  // 4 relations of one (b,i,j)
    float p0 = __fdividef(mm, 1.0f + __expf(-v.x));
    float p1 = __fdividef(mm, 1.0f + __expf(-v.y));
    float p2 = __fdividef(mm, 1.0f + __expf(-v.z));
    float p3 = __fdividef(mm, 1.0f + __expf(-v.w));
    g_relh[(b * R_ + 0) * N_ * N_ + rem] = __float2half(p0);
    g_relh[(b * R_ + 1) * N_ * N_ + rem] = __float2half(p1);
    g_relh[(b * R_ + 2) * N_ * N_ + rem] = __float2half(p2);
    g_relh[(b * R_ + 3) * N_ * N_ + rem] = __float2half(p3);
}

// ---------------- Pass 2: cubic relu contraction + fused final reduce ----------
// Grid: x = (a,b) tile (16), y = c-split (16), z = slice (8). 256 threads.
// Thread: 8x8 fp16 M_ab tile as 8x4 half2 regs; 8 half2 accs -> 4 f32.
__global__ void __launch_bounds__(256, 3)
trans_relu_kernel(float* __restrict__ out) {
    const int tile = blockIdx.x;      // 0..15
    const int cblk = blockIdx.y;      // 0..15
    const int sl   = blockIdx.z;      // 0..7
    const __half* __restrict__ M = g_relh + sl * N_ * N_;

    const int a0 = (tile / NT) * 128;
    const int b0 = (tile % NT) * 128;
    const int c0 = cblk * (N_ / CS);  // 32 c's per CTA

    const int tid = threadIdx.x;
    const int tx  = tid & 15;         // b sub-tile
    const int ty  = tid >> 4;         // a sub-tile

    // sA: NEGATED natural row-major copy: sA[a][c] = -M[a0+a][c0+c]  (8 KB)
    // sB: transposed copy:                sB[c][b] =  M[b0+b][c0+c]  (8 KB)
    __shared__ __align__(16) __half sA[128][32];
    __shared__ __align__(16) __half sB[32][128];

    // 8x8 M_ab tile packed as half2 (j,j+1) pairs: 32 regs.
    __half2 mab2[8][4];
#pragma unroll
    for (int i = 0; i < 8; ++i) {
        uint4 q = *(const uint4*)(M + (a0 + ty * 8 + i) * N_ + b0 + tx * 8);
        mab2[i][0] = *(__half2*)&q.x; mab2[i][1] = *(__half2*)&q.y;
        mab2[i][2] = *(__half2*)&q.z; mab2[i][3] = *(__half2*)&q.w;
    }

    // Stage: each thread handles 32 c-values of one A-row or one B-row.
    {
        const int  sr  = tid & 127;
        const bool isB = tid >= 128;
        const __half* rowp = M + ((isB ? b0 : a0) + sr) * N_ + c0;
        uint4 v0 = ((const uint4*)rowp)[0];
        uint4 v1 = ((const uint4*)rowp)[1];
        uint4 v2 = ((const uint4*)rowp)[2];
        uint4 v3 = ((const uint4*)rowp)[3];
        if (!isB) {
            // negate (sign-XOR, alu pipe) and store 4 x STS.128
            uint32_t w[16];
            *(uint4*)&w[0]  = v0; *(uint4*)&w[4]  = v1;
            *(uint4*)&w[8]  = v2; *(uint4*)&w[12] = v3;
#pragma unroll
            for (int k = 0; k < 16; ++k) w[k] ^= 0x80008000u;
            uint4* dst = (uint4*)&sA[sr][0];
            dst[0] = *(uint4*)&w[0];  dst[1] = *(uint4*)&w[4];
            dst[2] = *(uint4*)&w[8];  dst[3] = *(uint4*)&w[12];
        } else {
            __half h[32];
            *(uint4*)&h[0]  = v0; *(uint4*)&h[8]  = v1;
            *(uint4*)&h[16] = v2; *(uint4*)&h[24] = v3;
#pragma unroll
            for (int k = 0; k < 32; ++k) sB[k][sr] = h[k];
        }
    }
    __syncthreads();

    float facc[4];
#pragma unroll
    for (int p = 0; p < 4; ++p) facc[p] = 0.0f;

    // Mainloop: 4 blocks of 8 c's (processed 2 c's at a time);
    // fp32 promotion between blocks.
#pragma unroll
    for (int cb = 0; cb < 32; cb += 8) {
        __half2 hacc[8];                   // per-i accs: <=32 terms each
#pragma unroll
        for (int i = 0; i < 8; ++i) hacc[i] = __float2half2_rn(0.0f);

#pragma unroll
        for (int cc = 0; cc < 8; cc += 2) {
            const int c = cb + cc;
            // A: 8 x LDS.U32 -> {-a_i(c), -a_i(c+1)} (2-addr broadcast)
            uint32_t aw[8];
#pragma unroll
            for (int i = 0; i < 8; ++i)
                aw[i] = *(const uint32_t*)&sA[ty * 8 + i][c];
            // B: 2 x LDS.128 -> b pairs for c and c+1
            uint4 Bv0 = *(const uint4*)&sB[c][tx * 8];
            uint4 Bv1 = *(const uint4*)&sB[c + 1][tx * 8];
            __half2 bc0[4], bc1[4];
            bc0[0] = *(__half2*)&Bv0.x; bc0[1] = *(__half2*)&Bv0.y;
            bc0[2] = *(__half2*)&Bv0.z; bc0[3] = *(__half2*)&Bv0.w;
            bc1[0] = *(__half2*)&Bv1.x; bc1[1] = *(__half2*)&Bv1.y;
            bc1[2] = *(__half2*)&Bv1.z; bc1[3] = *(__half2*)&Bv1.w;
#pragma unroll
            for (int i = 0; i < 8; ++i) {
                __half2 ap = *(__half2*)&aw[i];
                __half2 aL = __low2half2(ap);    // {-a_i(c),  -a_i(c) }
                __half2 aH = __high2half2(ap);   // {-a_i(c+1),-a_i(c+1)}
#pragma unroll
                for (int jp = 0; jp < 4; ++jp) {
                    // fma.rn.relu.f16x2: 2 fma-pipe instrs per half2 pair.
                    hacc[i] = __hadd2(hacc[i],
                                      __hfma2_relu(aL, bc0[jp], mab2[i][jp]));
                    hacc[i] = __hadd2(hacc[i],
                                      __hfma2_relu(aH, bc1[jp], mab2[i][jp]));
                }
            }
        }

        // promote block accumulators to fp32 (pairwise into 4 accs)
#pragma unroll
        for (int i = 0; i < 8; i += 2) {
            __half2 hsum = __hadd2(hacc[i], hacc[i + 1]);   // <=64, fp16-safe
            facc[i >> 1] += __low2float(hsum) + __high2float(hsum);
        }
    }

    // Deterministic block reduction.
    float tsum = facc[0] + facc[1] + facc[2] + facc[3];
#pragma unroll
    for (int off = 16; off > 0; off >>= 1)
        tsum += __shfl_down_sync(0xFFFFFFFFu, tsum, off);

    __shared__ float wred[8];
    if ((tid & 31) == 0) wred[tid >> 5] = tsum;
    __syncthreads();

    // Publish partial, then elect the last-finishing CTA to do the final sum.
    __shared__ bool amLast;
    if (tid == 0) {
        float s = 0.0f;
#pragma unroll
        for (int w = 0; w < 8; ++w) s += wred[w];
        const int part = ((sl * CS + cblk) * (NT * NT)) + tile;
        g_part[part] = s;
        __threadfence();
        unsigned ticket = atomicAdd(&g_ctr, 1u);
        amLast = (ticket == NCTA - 1);
    }
    __syncthreads();

    if (amLast) {
        // Fixed-order deterministic final reduce over all 2048 partials.
        double s = 0.0;
#pragma unroll
        for (int k = 0; k < NCTA / 256; ++k)
            s += (double)g_part[tid + k * 256];
#pragma unroll
        for (int off = 16; off > 0; off >>= 1)
            s += __shfl_down_sync(0xFFFFFFFFu, s, off);
        __shared__ double dw[8];
        if ((tid & 31) == 0) dw[tid >> 5] = s;
        __syncthreads();
        if (tid == 0) {
            double tot = 0.0;
#pragma unroll
            for (int w = 0; w < 8; ++w) tot += dw[w];
            out[0] = (float)(tot / (double)(R_ * B_));
            g_ctr = 0;   // reset for next graph replay
        }
    }
}

extern "C" void kernel_launch(void* const* d_in, const int* in_sizes, int n_in,
                              void* d_out, int out_size) {
    const float* logits = (const float*)d_in[0];
    const int*   masks  = (const int*)d_in[1];
    float*       out    = (float*)d_out;

    sigmoid_mask_kernel<<<(B_ * N_ * N_ + 255) / 256, 256>>>(logits, masks);

    dim3 g2(NT * NT, CS, S_);
    trans_relu_kernel<<<g2, 256>>>(out);
}

// round 9
// speedup vs baseline: 1.0552x; 1.0306x over previous
#include <cuda_runtime.h>
#include <cuda_fp16.h>
#include <cstdint>

// LogicalConsistencyLoss: out = sum_{s,a,b,c} relu(M_ab - M_ac*M_bc) / (R*B)
// where M = fp16(sigmoid(logits)) * mask_a * mask_b per (batch,relation) slice.
// R9: CS 16->8 (1024 CTAs of 64 c's, 2.3 waves) -- generation-count cut.
//     Mainloop identical to R6 (best measured). 48KB smem, reduce scratch
//     aliased into sA after mainloop.

#define B_ 2
#define N_ 512
#define R_ 4
#define S_ (B_ * R_)                   // 8 slices
#define NT (N_ / 128)                  // 4 tiles per dim
#define CS 8                           // c-split: 64 c's per CTA
#define NCTA (NT * NT * CS * S_)       // 1024 cubic CTAs / partials

__device__ __half    g_relh[S_ * N_ * N_];   // 4 MB scratch (L2-resident)
__device__ float     g_part[NCTA];
__device__ unsigned  g_ctr;                  // zero-init; reset by last CTA

// ---------------- Pass 1: sigmoid + mask -> fp16, de-interleave R ----------------
__global__ void sigmoid_mask_kernel(const float* __restrict__ logits,
                                    const int*   __restrict__ masks) {
    int idx = blockIdx.x * blockDim.x + threadIdx.x;  // over B*N*N
    if (idx >= B_ * N_ * N_) return;
    int b   = idx / (N_ * N_);
    int rem = idx - b * (N_ * N_);
    int i   = rem / N_;
    int j   = rem - i * N_;
    float mm = (masks[b * N_ + i] > 0 && masks[b * N_ + j] > 0) ? 1.0f : 0.0f;
    float4 v = ((const float4*)logits)[idx];  // 4 relations of one (b,i,j)
    float p0 = __fdividef(mm, 1.0f + __expf(-v.x));
    float p1 = __fdividef(mm, 1.0f + __expf(-v.y));
    float p2 = __fdividef(mm, 1.0f + __expf(-v.z));
    float p3 = __fdividef(mm, 1.0f + __expf(-v.w));
    g_relh[(b * R_ + 0) * N_ * N_ + rem] = __float2half(p0);
    g_relh[(b * R_ + 1) * N_ * N_ + rem] = __float2half(p1);
    g_relh[(b * R_ + 2) * N_ * N_ + rem] = __float2half(p2);
    g_relh[(b * R_ + 3) * N_ * N_ + rem] = __float2half(p3);
}

// ---------------- Pass 2: cubic relu contraction + fused final reduce ----------
// Grid: x = (a,b) tile (16), y = c-split (8), z = slice (8). 256 threads.
// Thread: 8x8 fp16 M_ab tile as 8x4 half2 regs; 8 half2 accs -> 4 f32.
__global__ void __launch_bounds__(256, 3)
trans_relu_kernel(float* __restrict__ out) {
    const int tile = blockIdx.x;      // 0..15
    const int cblk = blockIdx.y;      // 0..7
    const int sl   = blockIdx.z;      // 0..7
    const __half* __restrict__ M = g_relh + sl * N_ * N_;

    const int a0 = (tile / NT) * 128;
    const int b0 = (tile % NT) * 128;
    const int c0 = cblk * (N_ / CS);  // 64 c's per CTA

    const int tid = threadIdx.x;
    const int tx  = tid & 15;         // b sub-tile
    const int ty  = tid >> 4;         // a sub-tile

    // All 64 c's staged once (48 KB total = static smem limit).
    // sA holds NEGATED + DUPLICATED values: sA[c][2a]=sA[c][2a+1] = -M[a0+a][c]
    // so uint4 LDS yields 4 ready {-a,-a} half2 broadcast pairs.
    __shared__ __align__(16) __half sA[64][256];   // 32 KB
    __shared__ __align__(16) __half sB[64][128];   // 16 KB
    // Reduction scratch aliased into sA after the mainloop (post-sync).
    float*  wred = reinterpret_cast<float*>(&sA[0][0]);    // 8 floats
    double* dw   = reinterpret_cast<double*>(&sA[1][0]);   // 8 doubles
    int*    lastf= reinterpret_cast<int*>(&sA[2][0]);      // amLast flag

    // 8x8 M_ab tile packed as half2 (j,j+1) pairs: 32 regs.
    __half2 mab2[8][4];
#pragma unroll
    for (int i = 0; i < 8; ++i) {
        uint4 q = *(const uint4*)(M + (a0 + ty * 8 + i) * N_ + b0 + tx * 8);
        mab2[i][0] = *(__half2*)&q.x; mab2[i][1] = *(__half2*)&q.y;
        mab2[i][2] = *(__half2*)&q.z; mab2[i][3] = *(__half2*)&q.w;
    }

    // Stage: each thread handles 64 c-values of one A-row or one B-row,
    // in two 32-c halves (keeps prologue register footprint at R6 level).
    {
        const int  sr  = tid & 127;
        const bool isB = tid >= 128;
        const __half* rowp = M + ((isB ? b0 : a0) + sr) * N_ + c0;
#pragma unroll
        for (int hfp = 0; hfp < 2; ++hfp) {
            uint4 v0 = ((const uint4*)rowp)[4 * hfp + 0];
            uint4 v1 = ((const uint4*)rowp)[4 * hfp + 1];
            uint4 v2 = ((const uint4*)rowp)[4 * hfp + 2];
            uint4 v3 = ((const uint4*)rowp)[4 * hfp + 3];
            __half h[32];
            *(uint4*)&h[0]  = v0; *(uint4*)&h[8]  = v1;
            *(uint4*)&h[16] = v2; *(uint4*)&h[24] = v3;
            const int cbase = 32 * hfp;
            if (!isB) {
#pragma unroll
                for (int k = 0; k < 32; ++k) {
                    __half2 p = __half2half2(__hneg(h[k]));
                    *(uint32_t*)&sA[cbase + k][2 * sr] = *(uint32_t*)&p;
                }
            } else {
#pragma unroll
                for (int k = 0; k < 32; ++k) sB[cbase + k][sr] = h[k];
            }
        }
    }
    __syncthreads();

    float facc[4];
#pragma unroll
    for (int p = 0; p < 4; ++p) facc[p] = 0.0f;

    // Mainloop: 8 blocks of 8 c's; fp32 promotion between blocks.
#pragma unroll 2
    for (int cb = 0; cb < 64; cb += 8) {
        __half2 hacc[8];                   // per-i accs: <=32 terms each
#pragma unroll
        for (int i = 0; i < 8; ++i) hacc[i] = __float2half2_rn(0.0f);

#pragma unroll
        for (int cc = 0; cc < 8; ++cc) {
            const int c = cb + cc;
            uint4 A0 = *(const uint4*)&sA[c][ty * 16];
            uint4 A1 = *(const uint4*)&sA[c][ty * 16 + 8];
            uint4 Bv = *(const uint4*)&sB[c][tx * 8];
            __half2 a2[8], b2[4];
            a2[0] = *(__half2*)&A0.x; a2[1] = *(__half2*)&A0.y;
            a2[2] = *(__half2*)&A0.z; a2[3] = *(__half2*)&A0.w;
            a2[4] = *(__half2*)&A1.x; a2[5] = *(__half2*)&A1.y;
            a2[6] = *(__half2*)&A1.z; a2[7] = *(__half2*)&A1.w;
            b2[0] = *(__half2*)&Bv.x; b2[1] = *(__half2*)&Bv.y;
            b2[2] = *(__half2*)&Bv.z; b2[3] = *(__half2*)&Bv.w;
#pragma unroll
            for (int i = 0; i < 8; ++i) {
#pragma unroll
                for (int jp = 0; jp < 4; ++jp) {
                    // fma.rn.relu.f16x2: 2 fma-pipe instrs per half2,
                    // zero alu-pipe work.
                    hacc[i] = __hadd2(hacc[i],
                                      __hfma2_relu(a2[i], b2[jp], mab2[i][jp]));
                }
            }
        }

        // promote block accumulators to fp32 (pairwise into 4 accs)
#pragma unroll
        for (int i = 0; i < 8; i += 2) {
            __half2 hsum = __hadd2(hacc[i], hacc[i + 1]);   // <=64, fp16-safe
            facc[i >> 1] += __low2float(hsum) + __high2float(hsum);
        }
    }

    // Deterministic block reduction.
    float tsum = facc[0] + facc[1] + facc[2] + facc[3];
#pragma unroll
    for (int off = 16; off > 0; off >>= 1)
        tsum += __shfl_down_sync(0xFFFFFFFFu, tsum, off);

    __syncthreads();   // release sA before aliased reuse
    if ((tid & 31) == 0) wred[tid >> 5] = tsum;
    __syncthreads();

    // Publish partial, then elect the last-finishing CTA to do the final sum.
    if (tid == 0) {
        float s = 0.0f;
#pragma unroll
        for (int w = 0; w < 8; ++w) s += wred[w];
        const int part = ((sl * CS + cblk) * (NT * NT)) + tile;
        g_part[part] = s;
        __threadfence();
        unsigned ticket = atomicAdd(&g_ctr, 1u);
        lastf[0] = (ticket == NCTA - 1) ? 1 : 0;
    }
    __syncthreads();

    if (lastf[0]) {
        // Fixed-order deterministic final reduce over all 1024 partials.
        double s = 0.0;
#pragma unroll
        for (int k = 0; k < NCTA / 256; ++k)
            s += (double)g_part[tid + k * 256];
#pragma unroll
        for (int off = 16; off > 0; off >>= 1)
            s += __shfl_down_sync(0xFFFFFFFFu, s, off);
        if ((tid & 31) == 0) dw[tid >> 5] = s;
        __syncthreads();
        if (tid == 0) {
            double tot = 0.0;
#pragma unroll
            for (int w = 0; w < 8; ++w) tot += dw[w];
            out[0] = (float)(tot / (double)(R_ * B_));
            g_ctr = 0;   // reset for next graph replay
        }
    }
}

extern "C" void kernel_launch(void* const* d_in, const int* in_sizes, int n_in,
                              void* d_out, int out_size) {
    const float* logits = (const float*)d_in[0];
    const int*   masks  = (const int*)d_in[1];
    float*       out    = (float*)d_out;

    sigmoid_mask_kernel<<<(B_ * N_ * N_ + 255) / 256, 256>>>(logits, masks);

    dim3 g2(NT * NT, CS, S_);
    trans_relu_kernel<<<g2, 256>>>(out);
}

// round 10
// speedup vs baseline: 1.0556x; 1.0004x over previous
#include <cuda_runtime.h>
#include <cuda_fp16.h>
#include <cstdint>

// LogicalConsistencyLoss: out = sum_{s,a,b,c} relu(M_ab - M_ac*M_bc) / (R*B)
// where M = fp16(sigmoid(logits)) * mask_a * mask_b per (batch,relation) slice.
// R10: occupancy 3->4 CTAs/SM. launch_bounds(256,4) + register diet
//      (target 64 regs). Mainloop = validated R6 form, CS=16 (24KB smem).

#define B_ 2
#define N_ 512
#define R_ 4
#define S_ (B_ * R_)                   // 8 slices
#define NT (N_ / 128)                  // 4 tiles per dim
#define CS 16                          // c-split: 32 c's per CTA
#define NCTA (NT * NT * CS * S_)       // 2048 cubic CTAs / partials

__device__ __half    g_relh[S_ * N_ * N_];   // 4 MB scratch (L2-resident)
__device__ float     g_part[NCTA];
__device__ unsigned  g_ctr;                  // zero-init; reset by last CTA

// ---------------- Pass 1: sigmoid + mask -> fp16, de-interleave R ----------------
__global__ void sigmoid_mask_kernel(const float* __restrict__ logits,
                                    const int*   __restrict__ masks) {
    int idx = blockIdx.x * blockDim.x + threadIdx.x;  // over B*N*N
    if (idx >= B_ * N_ * N_) return;
    int b   = idx / (N_ * N_);
    int rem = idx - b * (N_ * N_);
    int i   = rem / N_;
    int j   = rem - i * N_;
    float mm = (masks[b * N_ + i] > 0 && masks[b * N_ + j] > 0) ? 1.0f : 0.0f;
    float4 v = ((const float4*)logits)[idx];  // 4 relations of one (b,i,j)
    float p0 = __fdividef(mm, 1.0f + __expf(-v.x));
    float p1 = __fdividef(mm, 1.0f + __expf(-v.y));
    float p2 = __fdividef(mm, 1.0f + __expf(-v.z));
    float p3 = __fdividef(mm, 1.0f + __expf(-v.w));
    g_relh[(b * R_ + 0) * N_ * N_ + rem] = __float2half(p0);
    g_relh[(b * R_ + 1) * N_ * N_ + rem] = __float2half(p1);
    g_relh[(b * R_ + 2) * N_ * N_ + rem] = __float2half(p2);
    g_relh[(b * R_ + 3) * N_ * N_ + rem] = __float2half(p3);
}

// ---------------- Pass 2: cubic relu contraction + fused final reduce ----------
// Grid: x = (a,b) tile (16), y = c-split (16), z = slice (8). 256 threads.
// Thread: 8x8 fp16 M_ab tile as 8x4 half2 regs; 8 half2 accs -> 2 f32.
__global__ void __launch_bounds__(256, 4)
trans_relu_kernel(float* __restrict__ out) {
    const int tile = blockIdx.x;      // 0..15
    const int cblk = blockIdx.y;      // 0..15
    const int sl   = blockIdx.z;      // 0..7
    const __half* __restrict__ M = g_relh + sl * N_ * N_;

    const int a0 = (tile / NT) * 128;
    const int b0 = (tile % NT) * 128;
    const int c0 = cblk * (N_ / CS);  // 32 c's per CTA

    const int tid = threadIdx.x;
    const int tx  = tid & 15;         // b sub-tile
    const int ty  = tid >> 4;         // a sub-tile

    // All 32 c's staged once.
    // sA holds NEGATED + DUPLICATED values: sA[c][2a]=sA[c][2a+1] = -M[a0+a][c]
    // so uint4 LDS yields 4 ready {-a,-a} half2 broadcast pairs.
    __shared__ __align__(16) __half sA[32][256];   // 16 KB
    __shared__ __align__(16) __half sB[32][128];   //  8 KB
    // Reduction scratch aliased into sA after the mainloop (post-sync).
    float*  wred  = reinterpret_cast<float*>(&sA[0][0]);   // 8 floats
    double* dw    = reinterpret_cast<double*>(&sA[1][0]);  // 8 doubles
    int*    lastf = reinterpret_cast<int*>(&sA[2][0]);     // amLast flag

    // 8x8 M_ab tile packed as half2 (j,j+1) pairs: 32 regs.
    __half2 mab2[8][4];
#pragma unroll
    for (int i = 0; i < 8; ++i) {
        uint4 q = *(const uint4*)(M + (a0 + ty * 8 + i) * N_ + b0 + tx * 8);
        mab2[i][0] = *(__half2*)&q.x; mab2[i][1] = *(__half2*)&q.y;
        mab2[i][2] = *(__half2*)&q.z; mab2[i][3] = *(__half2*)&q.w;
    }

    // Stage: each thread handles 32 c-values of one A-row or one B-row,
    // one uint4 (8 c's) at a time to keep register liveness low.
    {
        const int  sr  = tid & 127;
        const bool isB = tid >= 128;
        const __half* rowp = M + ((isB ? b0 : a0) + sr) * N_ + c0;
#pragma unroll
        for (int q = 0; q < 4; ++q) {
            uint4 v = ((const uint4*)rowp)[q];
            __half h[8];
            *(uint4*)&h[0] = v;
            const int cbase = 8 * q;
            if (!isB) {
#pragma unroll
                for (int k = 0; k < 8; ++k) {
                    __half2 p = __half2half2(__hneg(h[k]));
                    *(uint32_t*)&sA[cbase + k][2 * sr] = *(uint32_t*)&p;
                }
            } else {
#pragma unroll
                for (int k = 0; k < 8; ++k) sB[cbase + k][sr] = h[k];
            }
        }
    }
    __syncthreads();

    float facc[2] = {0.0f, 0.0f};

    // Mainloop: 4 blocks of 8 c's; fp32 promotion between blocks.
#pragma unroll
    for (int cb = 0; cb < 32; cb += 8) {
        __half2 hacc[8];                   // per-i accs: <=32 terms each
#pragma unroll
        for (int i = 0; i < 8; ++i) hacc[i] = __float2half2_rn(0.0f);

#pragma unroll
        for (int cc = 0; cc < 8; ++cc) {
            const int c = cb + cc;
            uint4 A0 = *(const uint4*)&sA[c][ty * 16];
            uint4 A1 = *(const uint4*)&sA[c][ty * 16 + 8];
            uint4 Bv = *(const uint4*)&sB[c][tx * 8];
            __half2 a2[8], b2[4];
            a2[0] = *(__half2*)&A0.x; a2[1] = *(__half2*)&A0.y;
            a2[2] = *(__half2*)&A0.z; a2[3] = *(__half2*)&A0.w;
            a2[4] = *(__half2*)&A1.x; a2[5] = *(__half2*)&A1.y;
            a2[6] = *(__half2*)&A1.z; a2[7] = *(__half2*)&A1.w;
            b2[0] = *(__half2*)&Bv.x; b2[1] = *(__half2*)&Bv.y;
            b2[2] = *(__half2*)&Bv.z; b2[3] = *(__half2*)&Bv.w;
#pragma unroll
            for (int i = 0; i < 8; ++i) {
#pragma unroll
                for (int jp = 0; jp < 4; ++jp) {
                    // fma.rn.relu.f16x2: 2 fma-pipe instrs per half2,
                    // zero alu-pipe work.
                    hacc[i] = __hadd2(hacc[i],
                                      __hfma2_relu(a2[i], b2[jp], mab2[i][jp]));
                }
            }
        }

        // promote block accumulators to fp32 (tree into 2 accs)
        __half2 h01 = __hadd2(hacc[0], hacc[1]);
        __half2 h23 = __hadd2(hacc[2], hacc[3]);
        __half2 h45 = __hadd2(hacc[4], hacc[5]);
        __half2 h67 = __hadd2(hacc[6], hacc[7]);
        __half2 hA  = __hadd2(h01, h23);   // <=128 terms, max <128: fp16-safe
        __half2 hB  = __hadd2(h45, h67);
        facc[0] += __low2float(hA) + __high2float(hA);
        facc[1] += __low2float(hB) + __high2float(hB);
    }

    // Deterministic block reduction.
    float tsum = facc[0] + facc[1];
#pragma unroll
    for (int off = 16; off > 0; off >>= 1)
        tsum += __shfl_down_sync(0xFFFFFFFFu, tsum, off);

    __syncthreads();   // release sA before aliased reuse
    if ((tid & 31) == 0) wred[tid >> 5] = tsum;
    __syncthreads();

    // Publish partial, then elect the last-finishing CTA to do the final sum.
    if (tid == 0) {
        float s = 0.0f;
#pragma unroll
        for (int w = 0; w < 8; ++w) s += wred[w];
        const int part = ((sl * CS + cblk) * (NT * NT)) + tile;
        g_part[part] = s;
        __threadfence();
        unsigned ticket = atomicAdd(&g_ctr, 1u);
        lastf[0] = (ticket == NCTA - 1) ? 1 : 0;
    }
    __syncthreads();

    if (lastf[0]) {
        // Fixed-order deterministic final reduce over all 2048 partials.
        double s = 0.0;
#pragma unroll
        for (int k = 0; k < NCTA / 256; ++k)
            s += (double)g_part[tid + k * 256];
#pragma unroll
        for (int off = 16; off > 0; off >>= 1)
            s += __shfl_down_sync(0xFFFFFFFFu, s, off);
        if ((tid & 31) == 0) dw[tid >> 5] = s;
        __syncthreads();
        if (tid == 0) {
            double tot = 0.0;
#pragma unroll
            for (int w = 0; w < 8; ++w) tot += dw[w];
            out[0] = (float)(tot / (double)(R_ * B_));
            g_ctr = 0;   // reset for next graph replay
        }
    }
}

extern "C" void kernel_launch(void* const* d_in, const int* in_sizes, int n_in,
                              void* d_out, int out_size) {
    const float* logits = (const float*)d_in[0];
    const int*   masks  = (const int*)d_in[1];
    float*       out    = (float*)d_out;

    sigmoid_mask_kernel<<<(B_ * N_ * N_ + 255) / 256, 256>>>(logits, masks);

    dim3 g2(NT * NT, CS, S_);
    trans_relu_kernel<<<g2, 256>>>(out);
}